// round 16
// baseline (speedup 1.0000x reference)
#include <cuda_runtime.h>
#include <cuda_bf16.h>
#include <cstdint>

// ---------------------------------------------------------------------------
// GlobalMatchingTokenizer: 3 levels of efficient global matching attention.
// B=2, C={64,128,192}, H=W={64,32,16}, N=H*W, TOKEN_DIM=192, NUM_HEADS=4,
// HEAD_DIM=48, TOPK=128.
// Round 16: R15 base. attn: sampling-based threshold (256 samples, exact
// in-block sample rank) -> fused count+gather sweep with NO histogram
// atomics on the common path; R11 histogram select kept as exact fallback.
// ---------------------------------------------------------------------------

#define NH 4
#define HD 48
#define TD 192
#define KSEL 128
#define TN 16
#define CAP 256
#define SPAD 52

// Scratch (device globals; per-level disjoint offsets for stream overlap).
__device__ float g_S[143130624];
__device__ float g_Q[1990656];
__device__ float g_K[1990656];
__device__ float g_V[1990656];
__device__ float g_O[1990656];

// ---------------------------------------------------------------------------
// Kernel 1: QKV projection + positional encoding, n-tiled for weight reuse.
// grid = B*(N/TN), 384 threads.
// ---------------------------------------------------------------------------
__global__ void proj_kernel(const float* __restrict__ f1,
                            const float* __restrict__ f2,
                            const float* __restrict__ qw, const float* __restrict__ qb,
                            const float* __restrict__ kw, const float* __restrict__ kb,
                            const float* __restrict__ vw, const float* __restrict__ vb,
                            int C, int N, int W, size_t qoff)
{
    __shared__ float s1[TD][TN];
    __shared__ float s2[TD][TN];
    const int tid  = threadIdx.x;
    const int t    = tid % TD;
    const int half = tid / TD;
    const int nt = N / TN;
    const int n0 = (blockIdx.x % nt) * TN;
    const int b  = blockIdx.x / nt;

    for (int i = tid; i < C * TN; i += 384) {
        const int c = i / TN, j = i % TN;
        s1[c][j] = f1[((size_t)b * C + c) * N + n0 + j];
        s2[c][j] = f2[((size_t)b * C + c) * N + n0 + j];
    }
    __syncthreads();

    const int j0 = half * (TN / 2);
    float aq[TN / 2], ak[TN / 2], av[TN / 2];
    const float bq = qb[t], bk = kb[t], bv = vb[t];
    #pragma unroll
    for (int j = 0; j < TN / 2; ++j) { aq[j] = bq; ak[j] = bk; av[j] = bv; }

    for (int c = 0; c < C; ++c) {
        const float wq = qw[c * TD + t];
        const float wk = kw[c * TD + t];
        const float wv = vw[c * TD + t];
        #pragma unroll
        for (int j = 0; j < TN / 2; ++j) {
            const float a1 = s1[c][j0 + j];
            const float a2 = s2[c][j0 + j];
            aq[j] = fmaf(a1, wq, aq[j]);
            ak[j] = fmaf(a2, wk, ak[j]);
            av[j] = fmaf(a2, wv, av[j]);
        }
    }

    const float step = -9.210340371976184f / 96.0f;  // -ln(10000)/96
    const float div  = expf(step * (float)(t < 96 ? t : t - 96));
    #pragma unroll
    for (int j = 0; j < TN / 2; ++j) {
        const int n = n0 + j0 + j;
        const float pe = (t < 96) ? sinf((float)(n % W) * div)
                                  : cosf((float)(n / W) * div);
        aq[j] += pe;
        ak[j] += pe;
    }

    const int h = t / HD;
    const int d = t % HD;
    const size_t base = qoff + (((size_t)b * NH + h) * N + n0 + j0) * HD + d;
    #pragma unroll
    for (int j = 0; j < TN / 2; ++j) {
        g_Q[base + (size_t)j * HD] = aq[j];
        g_K[base + (size_t)j * HD] = ak[j];
        g_V[base + (size_t)j * HD] = av[j];
    }
}

// ---------------------------------------------------------------------------
// Kernel 2: scores GEMM (fp32 FFMA), 2 CTAs/SM (R15 occupancy fix).
// ---------------------------------------------------------------------------
__global__ void __launch_bounds__(256, 2) scores_kernel(int N, size_t soff, size_t qoff)
{
    __shared__ float Qs[128][SPAD];
    __shared__ float Ks[128][SPAD];

    const int bh = blockIdx.z;
    const float* __restrict__ Qb = g_Q + qoff + (size_t)bh * N * HD;
    const float* __restrict__ Kb = g_K + qoff + (size_t)bh * N * HD;
    float* __restrict__ Sb = g_S + soff + (size_t)bh * N * N;

    const int tid = threadIdx.x;
    const int rb = blockIdx.y * 128;
    const int cb = blockIdx.x * 128;

    for (int i = tid; i < 128 * 12; i += 256) {
        const int r = i / 12, q = (i % 12) * 4;
        *(float4*)&Qs[r][q] = *(const float4*)(Qb + (size_t)(rb + r) * HD + q);
        *(float4*)&Ks[r][q] = *(const float4*)(Kb + (size_t)(cb + r) * HD + q);
    }
    __syncthreads();

    const int ty = tid >> 4, tx = tid & 15;
    float acc[8][8] = {};

    #pragma unroll 4
    for (int kk = 0; kk < HD; ++kk) {
        float qv[8], kv[8];
        #pragma unroll
        for (int i = 0; i < 8; ++i) {
            qv[i] = Qs[ty + 16 * i][kk];
            kv[i] = Ks[tx + 16 * i][kk];
        }
        #pragma unroll
        for (int i = 0; i < 8; ++i)
            #pragma unroll
            for (int j = 0; j < 8; ++j)
                acc[i][j] = fmaf(qv[i], kv[j], acc[i][j]);
    }

    const float scale = 0.14433756729740643f;  // 1/sqrt(48)
    #pragma unroll
    for (int i = 0; i < 8; ++i) {
        const size_t ro = (size_t)(rb + ty + 16 * i) * N + cb + tx;
        #pragma unroll
        for (int j = 0; j < 8; ++j)
            Sb[ro + 16 * j] = acc[i][j] * scale;
    }
}

// ---------------------------------------------------------------------------
// Kernel 3: exact top-128 per row. Sampling threshold + fused count/gather
// (no histogram atomics); R11 histogram select as exact fallback.
// grid = B*NH*N rows, 256 threads. KSAMP: 12 (N=4096), 48 (1024), 192 (256).
// ---------------------------------------------------------------------------
__device__ __forceinline__ unsigned int floatToKey(float f)
{
    unsigned int u = __float_as_uint(f);
    return (u & 0x80000000u) ? ~u : (u | 0x80000000u);
}
__device__ __forceinline__ float keyToFloat(unsigned int u)
{
    unsigned int b = (u & 0x80000000u) ? (u & 0x7fffffffu) : ~u;
    return __uint_as_float(b);
}

__device__ __forceinline__ void pick_bin(const unsigned int* hist,
                                         int tid, int wid, int lane,
                                         int* wsum, int* s_need,
                                         unsigned int* s_bin, int* s_cand)
{
    const int h = (int)hist[tid];
    int x = h;
    #pragma unroll
    for (int off = 1; off < 32; off <<= 1) {
        const int y = __shfl_down_sync(0xffffffffu, x, off);
        if (lane + off < 32) x += y;
    }
    if (lane == 0) wsum[wid] = x;
    const int need = *s_need;
    __syncthreads();
    int above = x - h;
    for (int w = wid + 1; w < 8; ++w) above += wsum[w];
    if (above < need && above + h >= need) {
        *s_bin  = (unsigned int)tid;
        *s_need = need - above;
        *s_cand = h;
    }
    __syncthreads();
}

template <int CHN, bool GUARD, int KSAMP>
__global__ void __launch_bounds__(256) attn_kernel(int N, size_t soff, size_t qoff)
{
    extern __shared__ unsigned int keys[];
    __shared__ unsigned int hist[256];
    __shared__ __align__(16) unsigned int samp[256];
    __shared__ __align__(16) unsigned int ckey[CAP];
    __shared__ int          cidx[CAP];
    __shared__ float        wl[KSEL];
    __shared__ int          ml[KSEL];
    __shared__ float        accs2[4][HD];
    __shared__ int          wsum[8];
    __shared__ unsigned int uwred[8];
    __shared__ float        fwred[4];
    __shared__ int          s_need, s_cand, s_cnt, s_ccnt;
    __shared__ unsigned int s_bin, s_T0;

    const int tid  = threadIdx.x;
    const int wid  = tid >> 5, lane = tid & 31;
    const size_t row = blockIdx.x;
    const float* __restrict__ Srow = g_S + soff + row * (size_t)N;
    const int nv4 = N >> 2;

    if (tid == 0) { s_cnt = 0; s_ccnt = 0; }
    __syncthreads();

    // Sweep 1: uint4 load + key conversion + smem store + sample capture + max.
    unsigned int lmax = 0u;
    #pragma unroll
    for (int c = 0; c < CHN; ++c) {
        const int v4 = tid + 256 * c;
        if (!GUARD || v4 < nv4) {
            const float4 f = ((const float4*)Srow)[v4];
            uint4 k;
            k.x = floatToKey(f.x); k.y = floatToKey(f.y);
            k.z = floatToKey(f.z); k.w = floatToKey(f.w);
            ((uint4*)keys)[v4] = k;
            lmax = max(lmax, max(max(k.x, k.y), max(k.z, k.w)));
            if (CHN == 4) {
                if ((tid & 3) == 0) samp[(tid >> 2) + 64 * c] = k.x;   // elems 16m
            } else if (!GUARD) {
                samp[tid] = k.x;                                        // elems 4m
            } else {
                samp[4 * v4 + 0] = k.x; samp[4 * v4 + 1] = k.y;        // all elems
                samp[4 * v4 + 2] = k.z; samp[4 * v4 + 3] = k.w;
            }
        }
    }
    #pragma unroll
    for (int off = 16; off; off >>= 1)
        lmax = max(lmax, __shfl_down_sync(0xffffffffu, lmax, off));
    if (lane == 0) uwred[wid] = lmax;
    __syncthreads();
    unsigned int mk = uwred[0];
    #pragma unroll
    for (int w = 1; w < 8; ++w) mk = max(mk, uwred[w]);
    const float smax = keyToFloat(mk);

    // Exact rank of 256 samples (key desc, idx asc); T0 = KSAMP-th largest.
    {
        const unsigned int si = samp[tid];
        int r = 0;
        #pragma unroll 4
        for (int j4 = 0; j4 < 64; ++j4) {
            const uint4 s4 = ((const uint4*)samp)[j4];   // broadcast LDS
            const int j = 4 * j4;
            r += (s4.x > si) || (s4.x == si && (j + 0) < tid);
            r += (s4.y > si) || (s4.y == si && (j + 1) < tid);
            r += (s4.z > si) || (s4.z == si && (j + 2) < tid);
            r += (s4.w > si) || (s4.w == si && (j + 3) < tid);
        }
        if (r == KSAMP - 1) s_T0 = si;
    }
    __syncthreads();
    const unsigned int T0 = s_T0;

    // Sweep 2 (fused count + gather): candidates = all keys >= T0.
    #pragma unroll
    for (int c = 0; c < CHN; ++c) {
        const int v4 = tid + 256 * c;
        if (!GUARD || v4 < nv4) {
            const uint4 k = ((const uint4*)keys)[v4];
            const unsigned int kk[4] = {k.x, k.y, k.z, k.w};
            #pragma unroll
            for (int e = 0; e < 4; ++e) {
                if (kk[e] >= T0) {
                    const int slot = atomicAdd(&s_ccnt, 1);
                    if (slot < CAP) { ckey[slot] = kk[e]; cidx[slot] = 4 * v4 + e; }
                }
            }
        }
    }
    __syncthreads();

    int cc, needC;
    const bool good = (s_ccnt >= KSEL && s_ccnt <= CAP);

    if (good) {
        cc = s_ccnt;
        needC = KSEL;
    } else {
        // ------- Fallback: exact R11 histogram select -------
        if (tid == 0) { s_need = KSEL; s_cnt = 0; s_ccnt = 0; }
        hist[tid] = 0u;
        __syncthreads();

        #pragma unroll
        for (int c = 0; c < CHN; ++c) {
            const int v4 = tid + 256 * c;
            if (!GUARD || v4 < nv4) {
                const uint4 k = ((const uint4*)keys)[v4];
                atomicAdd(&hist[k.x >> 24], 1u);
                atomicAdd(&hist[k.y >> 24], 1u);
                atomicAdd(&hist[k.z >> 24], 1u);
                atomicAdd(&hist[k.w >> 24], 1u);
            }
        }
        __syncthreads();

        pick_bin(hist, tid, wid, lane, wsum, &s_need, &s_bin, &s_cand);

        int sh = 24;
        unsigned int pfx = s_bin;
        int cand = s_cand;

        while (cand > CAP && sh > 0) {
            const int nsh = sh - 8;
            hist[tid] = 0u;
            __syncthreads();
            #pragma unroll
            for (int c = 0; c < CHN; ++c) {
                const int v4 = tid + 256 * c;
                if (!GUARD || v4 < nv4) {
                    const uint4 k = ((const uint4*)keys)[v4];
                    const unsigned int kk[4] = {k.x, k.y, k.z, k.w};
                    #pragma unroll
                    for (int e = 0; e < 4; ++e)
                        if ((kk[e] >> sh) == pfx)
                            atomicAdd(&hist[(kk[e] >> nsh) & 255u], 1u);
                }
            }
            __syncthreads();
            pick_bin(hist, tid, wid, lane, wsum, &s_need, &s_bin, &s_cand);
            pfx = (pfx << 8) | s_bin;
            cand = s_cand;
            sh = nsh;
        }

        if (cand <= CAP) {
            #pragma unroll
            for (int c = 0; c < CHN; ++c) {
                const int v4 = tid + 256 * c;
                if (!GUARD || v4 < nv4) {
                    const uint4 k = ((const uint4*)keys)[v4];
                    const unsigned int kk[4] = {k.x, k.y, k.z, k.w};
                    #pragma unroll
                    for (int e = 0; e < 4; ++e) {
                        const unsigned int ub = kk[e] >> sh;
                        if (ub > pfx) {
                            const int slot = atomicAdd(&s_cnt, 1);
                            wl[slot] = __expf(keyToFloat(kk[e]) - smax);
                            ml[slot] = 4 * v4 + e;
                        } else if (ub == pfx) {
                            const int slot = atomicAdd(&s_ccnt, 1);
                            ckey[slot] = kk[e];
                            cidx[slot] = 4 * v4 + e;
                        }
                    }
                }
            }
            __syncthreads();
            cc = s_ccnt;
            needC = s_need;
        } else {
            // Pathological: > CAP keys equal on all 32 bits.
            #pragma unroll
            for (int c = 0; c < CHN; ++c) {
                const int v4 = tid + 256 * c;
                if (!GUARD || v4 < nv4) {
                    const uint4 k = ((const uint4*)keys)[v4];
                    const unsigned int kk[4] = {k.x, k.y, k.z, k.w};
                    #pragma unroll
                    for (int e = 0; e < 4; ++e) {
                        if (kk[e] > pfx) {
                            const int slot = atomicAdd(&s_cnt, 1);
                            wl[slot] = __expf(keyToFloat(kk[e]) - smax);
                            ml[slot] = 4 * v4 + e;
                        }
                    }
                }
            }
            __syncthreads();
            const int baseCnt = s_cnt;
            const int need = KSEL - baseCnt;
            const float wtie = __expf(keyToFloat(pfx) - smax);
            #pragma unroll
            for (int c = 0; c < CHN; ++c) {
                const int v4 = tid + 256 * c;
                if (!GUARD || v4 < nv4) {
                    const uint4 k = ((const uint4*)keys)[v4];
                    const unsigned int kk[4] = {k.x, k.y, k.z, k.w};
                    #pragma unroll
                    for (int e = 0; e < 4; ++e) {
                        if (kk[e] == pfx) {
                            const int idx = 4 * v4 + e;
                            int r = 0;
                            for (int j = 0; j < idx && r < need; ++j)
                                r += (keys[j] == pfx);
                            if (r < need) {
                                wl[baseCnt + r] = wtie;
                                ml[baseCnt + r] = idx;
                            }
                        }
                    }
                }
            }
            cc = 0;
            needC = 0;
            if (tid == 0) s_cnt = KSEL;
        }
    }
    __syncthreads();

    // Exact rank among candidates (key desc, index asc); keep rank < needC.
    if (tid < cc) {
        const unsigned int ki = ckey[tid];
        const int idi = cidx[tid];
        int r = 0;
        for (int j0 = 0; j0 < cc; j0 += 4) {
            const uint4 k4 = *(const uint4*)&ckey[j0];
            if (j0 + 0 < cc) { if (k4.x > ki || (k4.x == ki && cidx[j0 + 0] < idi)) ++r; }
            if (j0 + 1 < cc) { if (k4.y > ki || (k4.y == ki && cidx[j0 + 1] < idi)) ++r; }
            if (j0 + 2 < cc) { if (k4.z > ki || (k4.z == ki && cidx[j0 + 2] < idi)) ++r; }
            if (j0 + 3 < cc) { if (k4.w > ki || (k4.w == ki && cidx[j0 + 3] < idi)) ++r; }
        }
        if (r < needC) {
            const int slot = atomicAdd(&s_cnt, 1);
            wl[slot] = __expf(keyToFloat(ki) - smax);
            ml[slot] = idi;
        }
    }
    __syncthreads();   // all KSEL slots of wl/ml final

    // Z (shuffle + per-warp partials) and V accumulation, atomic-free.
    float z = (tid < KSEL) ? wl[tid] : 0.f;
    #pragma unroll
    for (int off = 16; off; off >>= 1)
        z += __shfl_down_sync(0xffffffffu, z, off);
    if (lane == 0 && wid < 4) fwred[wid] = z;

    const size_t bh = row / (size_t)N;
    const float* __restrict__ Vb = g_V + qoff + bh * (size_t)N * HD;
    if (tid < 192) {
        const int d = tid % HD;
        const int ch = tid / HD;
        float a = 0.f;
        #pragma unroll 4
        for (int i = ch; i < KSEL; i += 4)
            a = fmaf(wl[i], __ldg(&Vb[(size_t)ml[i] * HD + d]), a);
        accs2[ch][d] = a;
    }
    __syncthreads();

    if (tid < HD) {
        const float Z = fwred[0] + fwred[1] + fwred[2] + fwred[3];
        g_O[qoff + row * HD + tid] =
            (accs2[0][tid] + accs2[1][tid] + accs2[2][tid] + accs2[3][tid]) / Z;
    }
}

// ---------------------------------------------------------------------------
// Kernel 4: output projection, n-tiled, 384 threads.
// ---------------------------------------------------------------------------
__global__ void oproj_kernel(const float* __restrict__ ow,
                             const float* __restrict__ ob,
                             float* __restrict__ out, int N, size_t qoff)
{
    __shared__ float o[TD][TN + 1];
    const int tid  = threadIdx.x;
    const int t    = tid % TD;
    const int half = tid / TD;
    const int nt = N / TN;
    const int n0 = (blockIdx.x % nt) * TN;
    const int b  = blockIdx.x / nt;

    for (int i = tid; i < TD * TN; i += 384) {
        const int j  = i / TD;
        const int td = i % TD;
        const int h = td / HD, d = td % HD;
        o[td][j] = g_O[qoff + (((size_t)b * NH + h) * N + n0 + j) * HD + d];
    }
    __syncthreads();

    const int j0 = half * (TN / 2);
    float acc[TN / 2];
    const float bias = ob[t];
    #pragma unroll
    for (int j = 0; j < TN / 2; ++j) acc[j] = bias;

    for (int j = 0; j < TD; ++j) {
        const float w = ow[j * TD + t];
        #pragma unroll
        for (int jj = 0; jj < TN / 2; ++jj)
            acc[jj] = fmaf(o[j][j0 + jj], w, acc[jj]);
    }

    float4* op = (float4*)(out + ((size_t)b * TD + t) * N + n0 + j0);
    #pragma unroll
    for (int q = 0; q < TN / 8; ++q)
        op[q] = make_float4(acc[4 * q], acc[4 * q + 1], acc[4 * q + 2], acc[4 * q + 3]);
}

// ---------------------------------------------------------------------------
// Launch: 3 levels on 3 streams (fork-join, capture-legal) — R15 structure.
// ---------------------------------------------------------------------------
extern "C" void kernel_launch(void* const* d_in, const int* in_sizes, int n_in,
                              void* d_out, int out_size)
{
    (void)in_sizes; (void)n_in; (void)out_size;

    static cudaStream_t st1 = nullptr, st2 = nullptr;
    static cudaEvent_t evr = nullptr, evd1 = nullptr, evd2 = nullptr;
    static const bool inited = []() {
        cudaStreamCreateWithFlags(&st1, cudaStreamNonBlocking);
        cudaStreamCreateWithFlags(&st2, cudaStreamNonBlocking);
        cudaEventCreateWithFlags(&evr,  cudaEventDisableTiming);
        cudaEventCreateWithFlags(&evd1, cudaEventDisableTiming);
        cudaEventCreateWithFlags(&evd2, cudaEventDisableTiming);
        return true;
    }();
    (void)inited;

    const int    Cs[3]    = {64, 128, 192};
    const int    Hs[3]    = {64, 32, 16};
    const size_t soffs[3] = {0, 134217728, 142606336};
    const size_t qoffs[3] = {0, 1572864, 1966080};
    const size_t ooffs[3] = {0, 1572864, 1966080};
    cudaStream_t strs[3]  = {(cudaStream_t)0, st1, st2};

    // Fork.
    cudaEventRecord(evr, 0);
    cudaStreamWaitEvent(st1, evr, 0);
    cudaStreamWaitEvent(st2, evr, 0);

    for (int l = 0; l < 3; ++l) {
        const int C = Cs[l];
        const int H = Hs[l];
        const int N = H * H;
        const int B = 2;
        cudaStream_t st = strs[l];

        const float* f1 = (const float*)d_in[2 * l + 0];
        const float* f2 = (const float*)d_in[2 * l + 1];
        const int wb = 6 + 8 * l;
        const float* qw = (const float*)d_in[wb + 0];
        const float* qb = (const float*)d_in[wb + 1];
        const float* kw = (const float*)d_in[wb + 2];
        const float* kb = (const float*)d_in[wb + 3];
        const float* vw = (const float*)d_in[wb + 4];
        const float* vb = (const float*)d_in[wb + 5];
        const float* ow = (const float*)d_in[wb + 6];
        const float* ob = (const float*)d_in[wb + 7];

        float* outp = (float*)d_out + ooffs[l];

        proj_kernel<<<B * (N / TN), 384, 0, st>>>(f1, f2, qw, qb, kw, kb, vw, vb,
                                                  C, N, H, qoffs[l]);

        dim3 sg(N / 128, N / 128, B * NH);
        scores_kernel<<<sg, 256, 0, st>>>(N, soffs[l], qoffs[l]);

        const size_t ksmem = (size_t)N * sizeof(unsigned int);
        if (l == 0)
            attn_kernel<4, false, 12><<<B * NH * N, 256, ksmem, st>>>(N, soffs[l], qoffs[l]);
        else if (l == 1)
            attn_kernel<1, false, 48><<<B * NH * N, 256, ksmem, st>>>(N, soffs[l], qoffs[l]);
        else
            attn_kernel<1, true, 192><<<B * NH * N, 256, ksmem, st>>>(N, soffs[l], qoffs[l]);

        oproj_kernel<<<B * (N / TN), 384, 0, st>>>(ow, ob, outp, N, qoffs[l]);
    }

    // Join.
    cudaEventRecord(evd1, st1);
    cudaEventRecord(evd2, st2);
    cudaStreamWaitEvent((cudaStream_t)0, evd1, 0);
    cudaStreamWaitEvent((cudaStream_t)0, evd2, 0);
}

// round 17
// speedup vs baseline: 1.7531x; 1.7531x over previous
#include <cuda_runtime.h>
#include <cuda_bf16.h>
#include <cstdint>

// ---------------------------------------------------------------------------
// GlobalMatchingTokenizer: 3 levels of efficient global matching attention.
// B=2, C={64,128,192}, H=W={64,32,16}, N=H*W, TOKEN_DIM=192, NUM_HEADS=4,
// HEAD_DIM=48, TOPK=128.
// Round 17: R15 base (proven 968us). attn: first histogram uses a monotone
// CLAMPED fine bin (1/32-exponent granularity over [0.25,64)) so the
// boundary bin holds ~10 keys -> no refinement sweep on the common path.
// Full R15 histogram select retained as exact fallback (bin 0/255 or >CAP).
// ---------------------------------------------------------------------------

#define NH 4
#define HD 48
#define TD 192
#define KSEL 128
#define TN 16
#define CAP 256
#define SPAD 52
#define BINBASE 12192   // (0xBE800000u >> 18): key of +0.25f

// Scratch (device globals; per-level disjoint offsets for stream overlap).
__device__ float g_S[143130624];
__device__ float g_Q[1990656];
__device__ float g_K[1990656];
__device__ float g_V[1990656];
__device__ float g_O[1990656];

// ---------------------------------------------------------------------------
// Kernel 1: QKV projection + positional encoding, n-tiled for weight reuse.
// grid = B*(N/TN), 384 threads.
// ---------------------------------------------------------------------------
__global__ void proj_kernel(const float* __restrict__ f1,
                            const float* __restrict__ f2,
                            const float* __restrict__ qw, const float* __restrict__ qb,
                            const float* __restrict__ kw, const float* __restrict__ kb,
                            const float* __restrict__ vw, const float* __restrict__ vb,
                            int C, int N, int W, size_t qoff)
{
    __shared__ float s1[TD][TN];
    __shared__ float s2[TD][TN];
    const int tid  = threadIdx.x;
    const int t    = tid % TD;
    const int half = tid / TD;
    const int nt = N / TN;
    const int n0 = (blockIdx.x % nt) * TN;
    const int b  = blockIdx.x / nt;

    for (int i = tid; i < C * TN; i += 384) {
        const int c = i / TN, j = i % TN;
        s1[c][j] = f1[((size_t)b * C + c) * N + n0 + j];
        s2[c][j] = f2[((size_t)b * C + c) * N + n0 + j];
    }
    __syncthreads();

    const int j0 = half * (TN / 2);
    float aq[TN / 2], ak[TN / 2], av[TN / 2];
    const float bq = qb[t], bk = kb[t], bv = vb[t];
    #pragma unroll
    for (int j = 0; j < TN / 2; ++j) { aq[j] = bq; ak[j] = bk; av[j] = bv; }

    for (int c = 0; c < C; ++c) {
        const float wq = qw[c * TD + t];
        const float wk = kw[c * TD + t];
        const float wv = vw[c * TD + t];
        #pragma unroll
        for (int j = 0; j < TN / 2; ++j) {
            const float a1 = s1[c][j0 + j];
            const float a2 = s2[c][j0 + j];
            aq[j] = fmaf(a1, wq, aq[j]);
            ak[j] = fmaf(a2, wk, ak[j]);
            av[j] = fmaf(a2, wv, av[j]);
        }
    }

    const float step = -9.210340371976184f / 96.0f;  // -ln(10000)/96
    const float div  = expf(step * (float)(t < 96 ? t : t - 96));
    #pragma unroll
    for (int j = 0; j < TN / 2; ++j) {
        const int n = n0 + j0 + j;
        const float pe = (t < 96) ? sinf((float)(n % W) * div)
                                  : cosf((float)(n / W) * div);
        aq[j] += pe;
        ak[j] += pe;
    }

    const int h = t / HD;
    const int d = t % HD;
    const size_t base = qoff + (((size_t)b * NH + h) * N + n0 + j0) * HD + d;
    #pragma unroll
    for (int j = 0; j < TN / 2; ++j) {
        g_Q[base + (size_t)j * HD] = aq[j];
        g_K[base + (size_t)j * HD] = ak[j];
        g_V[base + (size_t)j * HD] = av[j];
    }
}

// ---------------------------------------------------------------------------
// Kernel 2: scores GEMM (fp32 FFMA), 2 CTAs/SM (R15 occupancy fix).
// ---------------------------------------------------------------------------
__global__ void __launch_bounds__(256, 2) scores_kernel(int N, size_t soff, size_t qoff)
{
    __shared__ float Qs[128][SPAD];
    __shared__ float Ks[128][SPAD];

    const int bh = blockIdx.z;
    const float* __restrict__ Qb = g_Q + qoff + (size_t)bh * N * HD;
    const float* __restrict__ Kb = g_K + qoff + (size_t)bh * N * HD;
    float* __restrict__ Sb = g_S + soff + (size_t)bh * N * N;

    const int tid = threadIdx.x;
    const int rb = blockIdx.y * 128;
    const int cb = blockIdx.x * 128;

    for (int i = tid; i < 128 * 12; i += 256) {
        const int r = i / 12, q = (i % 12) * 4;
        *(float4*)&Qs[r][q] = *(const float4*)(Qb + (size_t)(rb + r) * HD + q);
        *(float4*)&Ks[r][q] = *(const float4*)(Kb + (size_t)(cb + r) * HD + q);
    }
    __syncthreads();

    const int ty = tid >> 4, tx = tid & 15;
    float acc[8][8] = {};

    #pragma unroll 4
    for (int kk = 0; kk < HD; ++kk) {
        float qv[8], kv[8];
        #pragma unroll
        for (int i = 0; i < 8; ++i) {
            qv[i] = Qs[ty + 16 * i][kk];
            kv[i] = Ks[tx + 16 * i][kk];
        }
        #pragma unroll
        for (int i = 0; i < 8; ++i)
            #pragma unroll
            for (int j = 0; j < 8; ++j)
                acc[i][j] = fmaf(qv[i], kv[j], acc[i][j]);
    }

    const float scale = 0.14433756729740643f;  // 1/sqrt(48)
    #pragma unroll
    for (int i = 0; i < 8; ++i) {
        const size_t ro = (size_t)(rb + ty + 16 * i) * N + cb + tx;
        #pragma unroll
        for (int j = 0; j < 8; ++j)
            Sb[ro + 16 * j] = acc[i][j] * scale;
    }
}

// ---------------------------------------------------------------------------
// Kernel 3: exact top-128 per row.
// Sweep 1 builds a 256-bin histogram with a MONOTONE clamped fine bin
// (1/32-exponent steps over [0.25, 64)). If the picked bin is interior and
// holds <= CAP keys (common case), gather directly -> 2 sweeps total.
// Otherwise: full R15 histogram select (exact fallback).
// ---------------------------------------------------------------------------
__device__ __forceinline__ unsigned int floatToKey(float f)
{
    unsigned int u = __float_as_uint(f);
    return (u & 0x80000000u) ? ~u : (u | 0x80000000u);
}
__device__ __forceinline__ float keyToFloat(unsigned int u)
{
    unsigned int b = (u & 0x80000000u) ? (u & 0x7fffffffu) : ~u;
    return __uint_as_float(b);
}
__device__ __forceinline__ unsigned int binClamp(unsigned int k)
{
    const int t = (int)(k >> 18) - BINBASE;
    return (unsigned int)max(0, min(255, t));
}

__device__ __forceinline__ void pick_bin(const unsigned int* hist,
                                         int tid, int wid, int lane,
                                         int* wsum, int* s_need,
                                         unsigned int* s_bin, int* s_cand)
{
    const int h = (int)hist[tid];
    int x = h;
    #pragma unroll
    for (int off = 1; off < 32; off <<= 1) {
        const int y = __shfl_down_sync(0xffffffffu, x, off);
        if (lane + off < 32) x += y;
    }
    if (lane == 0) wsum[wid] = x;
    const int need = *s_need;
    __syncthreads();
    int above = x - h;
    for (int w = wid + 1; w < 8; ++w) above += wsum[w];
    if (above < need && above + h >= need) {
        *s_bin  = (unsigned int)tid;
        *s_need = need - above;
        *s_cand = h;
    }
    __syncthreads();
}

template <int CHN, bool GUARD>
__global__ void __launch_bounds__(256) attn_kernel(int N, size_t soff, size_t qoff)
{
    extern __shared__ unsigned int keys[];
    __shared__ unsigned int hist[256];
    __shared__ __align__(16) unsigned int ckey[CAP];
    __shared__ int          cidx[CAP];
    __shared__ float        wl[KSEL];
    __shared__ int          ml[KSEL];
    __shared__ float        accs2[4][HD];
    __shared__ int          wsum[8];
    __shared__ unsigned int uwred[8];
    __shared__ float        fwred[4];
    __shared__ int          s_need, s_cand, s_cnt, s_ccnt;
    __shared__ unsigned int s_bin;

    const int tid  = threadIdx.x;
    const int wid  = tid >> 5, lane = tid & 31;
    const size_t row = blockIdx.x;
    const float* __restrict__ Srow = g_S + soff + row * (size_t)N;
    const int nv4 = N >> 2;

    hist[tid] = 0u;
    if (tid == 0) { s_need = KSEL; s_cnt = 0; s_ccnt = 0; }
    __syncthreads();

    // Sweep 1: uint4 load + key conversion + smem store + clamped-fine hist.
    unsigned int lmax = 0u;
    #pragma unroll
    for (int c = 0; c < CHN; ++c) {
        const int v4 = tid + 256 * c;
        if (!GUARD || v4 < nv4) {
            const float4 f = ((const float4*)Srow)[v4];
            uint4 k;
            k.x = floatToKey(f.x); k.y = floatToKey(f.y);
            k.z = floatToKey(f.z); k.w = floatToKey(f.w);
            ((uint4*)keys)[v4] = k;
            atomicAdd(&hist[binClamp(k.x)], 1u);
            atomicAdd(&hist[binClamp(k.y)], 1u);
            atomicAdd(&hist[binClamp(k.z)], 1u);
            atomicAdd(&hist[binClamp(k.w)], 1u);
            lmax = max(lmax, max(max(k.x, k.y), max(k.z, k.w)));
        }
    }
    #pragma unroll
    for (int off = 16; off; off >>= 1)
        lmax = max(lmax, __shfl_down_sync(0xffffffffu, lmax, off));
    if (lane == 0) uwred[wid] = lmax;
    __syncthreads();
    unsigned int mk = uwred[0];
    #pragma unroll
    for (int w = 1; w < 8; ++w) mk = max(mk, uwred[w]);
    const float smax = keyToFloat(mk);

    // Pick over the clamped-fine histogram.
    pick_bin(hist, tid, wid, lane, wsum, &s_need, &s_bin, &s_cand);

    const unsigned int fbin = s_bin;
    const bool good = (fbin != 0u && fbin != 255u && s_cand <= CAP);
    int cc = 0, needC = 0;

    if (good) {
        // Common path: gather winners (bin > fbin) and candidates (bin == fbin).
        needC = s_need;
        #pragma unroll
        for (int c = 0; c < CHN; ++c) {
            const int v4 = tid + 256 * c;
            if (!GUARD || v4 < nv4) {
                const uint4 k = ((const uint4*)keys)[v4];
                const unsigned int kk[4] = {k.x, k.y, k.z, k.w};
                #pragma unroll
                for (int e = 0; e < 4; ++e) {
                    const unsigned int ub = binClamp(kk[e]);
                    if (ub > fbin) {
                        const int slot = atomicAdd(&s_cnt, 1);
                        wl[slot] = __expf(keyToFloat(kk[e]) - smax);
                        ml[slot] = 4 * v4 + e;
                    } else if (ub == fbin) {
                        const int slot = atomicAdd(&s_ccnt, 1);
                        ckey[slot] = kk[e];
                        cidx[slot] = 4 * v4 + e;
                    }
                }
            }
        }
        __syncthreads();
        cc = s_ccnt;
    } else {
        // ---- Exact fallback: full R15 8-bit histogram select ----
        if (tid == 0) { s_need = KSEL; s_cnt = 0; s_ccnt = 0; }
        hist[tid] = 0u;
        __syncthreads();

        #pragma unroll
        for (int c = 0; c < CHN; ++c) {
            const int v4 = tid + 256 * c;
            if (!GUARD || v4 < nv4) {
                const uint4 k = ((const uint4*)keys)[v4];
                atomicAdd(&hist[k.x >> 24], 1u);
                atomicAdd(&hist[k.y >> 24], 1u);
                atomicAdd(&hist[k.z >> 24], 1u);
                atomicAdd(&hist[k.w >> 24], 1u);
            }
        }
        __syncthreads();

        pick_bin(hist, tid, wid, lane, wsum, &s_need, &s_bin, &s_cand);

        int sh = 24;
        unsigned int pfx = s_bin;
        int cand = s_cand;

        while (cand > CAP && sh > 0) {
            const int nsh = sh - 8;
            hist[tid] = 0u;
            __syncthreads();
            #pragma unroll
            for (int c = 0; c < CHN; ++c) {
                const int v4 = tid + 256 * c;
                if (!GUARD || v4 < nv4) {
                    const uint4 k = ((const uint4*)keys)[v4];
                    const unsigned int kk[4] = {k.x, k.y, k.z, k.w};
                    #pragma unroll
                    for (int e = 0; e < 4; ++e)
                        if ((kk[e] >> sh) == pfx)
                            atomicAdd(&hist[(kk[e] >> nsh) & 255u], 1u);
                }
            }
            __syncthreads();
            pick_bin(hist, tid, wid, lane, wsum, &s_need, &s_bin, &s_cand);
            pfx = (pfx << 8) | s_bin;
            cand = s_cand;
            sh = nsh;
        }

        if (cand <= CAP) {
            #pragma unroll
            for (int c = 0; c < CHN; ++c) {
                const int v4 = tid + 256 * c;
                if (!GUARD || v4 < nv4) {
                    const uint4 k = ((const uint4*)keys)[v4];
                    const unsigned int kk[4] = {k.x, k.y, k.z, k.w};
                    #pragma unroll
                    for (int e = 0; e < 4; ++e) {
                        const unsigned int ub = kk[e] >> sh;
                        if (ub > pfx) {
                            const int slot = atomicAdd(&s_cnt, 1);
                            wl[slot] = __expf(keyToFloat(kk[e]) - smax);
                            ml[slot] = 4 * v4 + e;
                        } else if (ub == pfx) {
                            const int slot = atomicAdd(&s_ccnt, 1);
                            ckey[slot] = kk[e];
                            cidx[slot] = 4 * v4 + e;
                        }
                    }
                }
            }
            __syncthreads();
            cc = s_ccnt;
            needC = s_need;
        } else {
            // Pathological: > CAP keys equal on all 32 bits.
            #pragma unroll
            for (int c = 0; c < CHN; ++c) {
                const int v4 = tid + 256 * c;
                if (!GUARD || v4 < nv4) {
                    const uint4 k = ((const uint4*)keys)[v4];
                    const unsigned int kk[4] = {k.x, k.y, k.z, k.w};
                    #pragma unroll
                    for (int e = 0; e < 4; ++e) {
                        if (kk[e] > pfx) {
                            const int slot = atomicAdd(&s_cnt, 1);
                            wl[slot] = __expf(keyToFloat(kk[e]) - smax);
                            ml[slot] = 4 * v4 + e;
                        }
                    }
                }
            }
            __syncthreads();
            const int baseCnt = s_cnt;
            const int need = KSEL - baseCnt;
            const float wtie = __expf(keyToFloat(pfx) - smax);
            #pragma unroll
            for (int c = 0; c < CHN; ++c) {
                const int v4 = tid + 256 * c;
                if (!GUARD || v4 < nv4) {
                    const uint4 k = ((const uint4*)keys)[v4];
                    const unsigned int kk[4] = {k.x, k.y, k.z, k.w};
                    #pragma unroll
                    for (int e = 0; e < 4; ++e) {
                        if (kk[e] == pfx) {
                            const int idx = 4 * v4 + e;
                            int r = 0;
                            for (int j = 0; j < idx && r < need; ++j)
                                r += (keys[j] == pfx);
                            if (r < need) {
                                wl[baseCnt + r] = wtie;
                                ml[baseCnt + r] = idx;
                            }
                        }
                    }
                }
            }
            cc = 0;
            needC = 0;
            if (tid == 0) s_cnt = KSEL;
        }
        __syncthreads();
    }

    // Exact rank among candidates (key desc, index asc); keep rank < needC.
    if (tid < cc) {
        const unsigned int ki = ckey[tid];
        const int idi = cidx[tid];
        int r = 0;
        for (int j0 = 0; j0 < cc; j0 += 4) {
            const uint4 k4 = *(const uint4*)&ckey[j0];
            if (j0 + 0 < cc) { if (k4.x > ki || (k4.x == ki && cidx[j0 + 0] < idi)) ++r; }
            if (j0 + 1 < cc) { if (k4.y > ki || (k4.y == ki && cidx[j0 + 1] < idi)) ++r; }
            if (j0 + 2 < cc) { if (k4.z > ki || (k4.z == ki && cidx[j0 + 2] < idi)) ++r; }
            if (j0 + 3 < cc) { if (k4.w > ki || (k4.w == ki && cidx[j0 + 3] < idi)) ++r; }
        }
        if (r < needC) {
            const int slot = atomicAdd(&s_cnt, 1);
            wl[slot] = __expf(keyToFloat(ki) - smax);
            ml[slot] = idi;
        }
    }
    __syncthreads();   // all KSEL slots of wl/ml final

    // Z (shuffle + per-warp partials) and V accumulation, atomic-free.
    float z = (tid < KSEL) ? wl[tid] : 0.f;
    #pragma unroll
    for (int off = 16; off; off >>= 1)
        z += __shfl_down_sync(0xffffffffu, z, off);
    if (lane == 0 && wid < 4) fwred[wid] = z;

    const size_t bh = row / (size_t)N;
    const float* __restrict__ Vb = g_V + qoff + bh * (size_t)N * HD;
    if (tid < 192) {
        const int d = tid % HD;
        const int ch = tid / HD;
        float a = 0.f;
        #pragma unroll 4
        for (int i = ch; i < KSEL; i += 4)
            a = fmaf(wl[i], __ldg(&Vb[(size_t)ml[i] * HD + d]), a);
        accs2[ch][d] = a;
    }
    __syncthreads();

    if (tid < HD) {
        const float Z = fwred[0] + fwred[1] + fwred[2] + fwred[3];
        g_O[qoff + row * HD + tid] =
            (accs2[0][tid] + accs2[1][tid] + accs2[2][tid] + accs2[3][tid]) / Z;
    }
}

// ---------------------------------------------------------------------------
// Kernel 4: output projection, n-tiled, 384 threads.
// ---------------------------------------------------------------------------
__global__ void oproj_kernel(const float* __restrict__ ow,
                             const float* __restrict__ ob,
                             float* __restrict__ out, int N, size_t qoff)
{
    __shared__ float o[TD][TN + 1];
    const int tid  = threadIdx.x;
    const int t    = tid % TD;
    const int half = tid / TD;
    const int nt = N / TN;
    const int n0 = (blockIdx.x % nt) * TN;
    const int b  = blockIdx.x / nt;

    for (int i = tid; i < TD * TN; i += 384) {
        const int j  = i / TD;
        const int td = i % TD;
        const int h = td / HD, d = td % HD;
        o[td][j] = g_O[qoff + (((size_t)b * NH + h) * N + n0 + j) * HD + d];
    }
    __syncthreads();

    const int j0 = half * (TN / 2);
    float acc[TN / 2];
    const float bias = ob[t];
    #pragma unroll
    for (int j = 0; j < TN / 2; ++j) acc[j] = bias;

    for (int j = 0; j < TD; ++j) {
        const float w = ow[j * TD + t];
        #pragma unroll
        for (int jj = 0; jj < TN / 2; ++jj)
            acc[jj] = fmaf(o[j][j0 + jj], w, acc[jj]);
    }

    float4* op = (float4*)(out + ((size_t)b * TD + t) * N + n0 + j0);
    #pragma unroll
    for (int q = 0; q < TN / 8; ++q)
        op[q] = make_float4(acc[4 * q], acc[4 * q + 1], acc[4 * q + 2], acc[4 * q + 3]);
}

// ---------------------------------------------------------------------------
// Launch: 3 levels on 3 streams (fork-join, capture-legal) — R15 structure.
// ---------------------------------------------------------------------------
extern "C" void kernel_launch(void* const* d_in, const int* in_sizes, int n_in,
                              void* d_out, int out_size)
{
    (void)in_sizes; (void)n_in; (void)out_size;

    static cudaStream_t st1 = nullptr, st2 = nullptr;
    static cudaEvent_t evr = nullptr, evd1 = nullptr, evd2 = nullptr;
    static const bool inited = []() {
        cudaStreamCreateWithFlags(&st1, cudaStreamNonBlocking);
        cudaStreamCreateWithFlags(&st2, cudaStreamNonBlocking);
        cudaEventCreateWithFlags(&evr,  cudaEventDisableTiming);
        cudaEventCreateWithFlags(&evd1, cudaEventDisableTiming);
        cudaEventCreateWithFlags(&evd2, cudaEventDisableTiming);
        return true;
    }();
    (void)inited;

    const int    Cs[3]    = {64, 128, 192};
    const int    Hs[3]    = {64, 32, 16};
    const size_t soffs[3] = {0, 134217728, 142606336};
    const size_t qoffs[3] = {0, 1572864, 1966080};
    const size_t ooffs[3] = {0, 1572864, 1966080};
    cudaStream_t strs[3]  = {(cudaStream_t)0, st1, st2};

    // Fork.
    cudaEventRecord(evr, 0);
    cudaStreamWaitEvent(st1, evr, 0);
    cudaStreamWaitEvent(st2, evr, 0);

    for (int l = 0; l < 3; ++l) {
        const int C = Cs[l];
        const int H = Hs[l];
        const int N = H * H;
        const int B = 2;
        cudaStream_t st = strs[l];

        const float* f1 = (const float*)d_in[2 * l + 0];
        const float* f2 = (const float*)d_in[2 * l + 1];
        const int wb = 6 + 8 * l;
        const float* qw = (const float*)d_in[wb + 0];
        const float* qb = (const float*)d_in[wb + 1];
        const float* kw = (const float*)d_in[wb + 2];
        const float* kb = (const float*)d_in[wb + 3];
        const float* vw = (const float*)d_in[wb + 4];
        const float* vb = (const float*)d_in[wb + 5];
        const float* ow = (const float*)d_in[wb + 6];
        const float* ob = (const float*)d_in[wb + 7];

        float* outp = (float*)d_out + ooffs[l];

        proj_kernel<<<B * (N / TN), 384, 0, st>>>(f1, f2, qw, qb, kw, kb, vw, vb,
                                                  C, N, H, qoffs[l]);

        dim3 sg(N / 128, N / 128, B * NH);
        scores_kernel<<<sg, 256, 0, st>>>(N, soffs[l], qoffs[l]);

        const size_t ksmem = (size_t)N * sizeof(unsigned int);
        if (l == 0)
            attn_kernel<4, false><<<B * NH * N, 256, ksmem, st>>>(N, soffs[l], qoffs[l]);
        else if (l == 1)
            attn_kernel<1, false><<<B * NH * N, 256, ksmem, st>>>(N, soffs[l], qoffs[l]);
        else
            attn_kernel<1, true><<<B * NH * N, 256, ksmem, st>>>(N, soffs[l], qoffs[l]);

        oproj_kernel<<<B * (N / TN), 384, 0, st>>>(ow, ob, outp, N, qoffs[l]);
    }

    // Join.
    cudaEventRecord(evd1, st1);
    cudaEventRecord(evd2, st2);
    cudaStreamWaitEvent((cudaStream_t)0, evd1, 0);
    cudaStreamWaitEvent((cudaStream_t)0, evd2, 0);
}